// round 5
// baseline (speedup 1.0000x reference)
#include <cuda_runtime.h>
#include <cuda_bf16.h>
#include <cstdint>

// Problem shape: n=4096, m=32768, d=128
#define N_FIX 4096
#define M_FIX 32768
#define D_FIX 128
#define TOT_TILES 8192          // (4096/128) * (32768/128)
#define CTAS 304
#define TPC 27                  // ceil(8192/304)
#define SCALE 28.0f             // int8 quant scale; product scale = 784
#define NEG_T 392               // 0.5 * 784
#define POS_T 784               // include pos iff acc < 784  (acc<=783 => sim<=0.99872<1-1e-5)
#define FINAL_SCALE (1.0f / (784.0f * 4096.0f))

#define ROWB 144                // padded smem row stride (bytes) per 128B tile row
#define TILE_SM (128 * ROWB)    // 18432 B

// smem layout (bytes)
#define SM_A     0
#define SM_B0    18432
#define SM_B1    36864
#define SM_LABA  55296
#define SM_LABB0 55808
#define SM_LABB1 56320
#define SM_WSUM  56832
#define SM_TOTAL 56896

// int8 scratch (allocation-free rule: __device__ globals)
__device__ char g_A8[N_FIX * D_FIX];
__device__ char g_B8[M_FIX * D_FIX];
__device__ int  g_labA[N_FIX];
__device__ int  g_labB[M_FIX];

// ---------------------------------------------------------------------------
// Prep: fp32 -> int8 quantization, label extraction (level 0), out zeroing
// ---------------------------------------------------------------------------
__device__ __forceinline__ uint32_t quant4(float4 v) {
    int a = __float2int_rn(v.x * SCALE); a = max(-127, min(127, a));
    int b = __float2int_rn(v.y * SCALE); b = max(-127, min(127, b));
    int c = __float2int_rn(v.z * SCALE); c = max(-127, min(127, c));
    int d = __float2int_rn(v.w * SCALE); d = max(-127, min(127, d));
    return (uint32_t)(a & 0xFF) | ((uint32_t)(b & 0xFF) << 8) |
           ((uint32_t)(c & 0xFF) << 16) | ((uint32_t)(d & 0xFF) << 24);
}

__global__ void prep_kernel(const float4* __restrict__ emb,
                            const long long* __restrict__ labels,
                            const float4* __restrict__ ref,
                            const long long* __restrict__ ref_labels,
                            float* __restrict__ out) {
    int tid = blockIdx.x * blockDim.x + threadIdx.x;
    int stride = gridDim.x * blockDim.x;
    if (tid == 0) out[0] = 0.0f;
    uint32_t* A32 = (uint32_t*)g_A8;
    uint32_t* B32 = (uint32_t*)g_B8;
    for (int i = tid; i < N_FIX * D_FIX / 4; i += stride)
        A32[i] = quant4(emb[i]);
    for (int i = tid; i < M_FIX * D_FIX / 4; i += stride)
        B32[i] = quant4(ref[i]);
    for (int i = tid; i < N_FIX; i += stride)
        g_labA[i] = (int)labels[(long long)i * 2];
    for (int i = tid; i < M_FIX; i += stride)
        g_labB[i] = (int)ref_labels[(long long)i * 2];
}

// ---------------------------------------------------------------------------
// PTX helpers
// ---------------------------------------------------------------------------
__device__ __forceinline__ uint32_t smem_u32(const void* p) {
    return (uint32_t)__cvta_generic_to_shared(p);
}
__device__ __forceinline__ void cp16(uint32_t saddr, const void* gaddr) {
    asm volatile("cp.async.cg.shared.global [%0], [%1], 16;" :: "r"(saddr), "l"(gaddr));
}
__device__ __forceinline__ void cp_commit() { asm volatile("cp.async.commit_group;"); }
__device__ __forceinline__ void cp_wait0()  { asm volatile("cp.async.wait_group 0;" ::: "memory"); }

__device__ __forceinline__ void ldsm_x4(uint32_t* r, uint32_t addr) {
    asm volatile("ldmatrix.sync.aligned.m8n8.x4.shared.b16 {%0,%1,%2,%3}, [%4];"
                 : "=r"(r[0]), "=r"(r[1]), "=r"(r[2]), "=r"(r[3]) : "r"(addr));
}

__device__ __forceinline__ void mma_s8(int* c, const uint32_t* a, uint32_t b0, uint32_t b1) {
    asm volatile(
        "mma.sync.aligned.m16n8k32.row.col.s32.s8.s8.s32 "
        "{%0,%1,%2,%3}, {%4,%5,%6,%7}, {%8,%9}, {%0,%1,%2,%3};"
        : "+r"(c[0]), "+r"(c[1]), "+r"(c[2]), "+r"(c[3])
        : "r"(a[0]), "r"(a[1]), "r"(a[2]), "r"(a[3]), "r"(b0), "r"(b1));
}

// load a 128x128 int8 tile into padded smem (1024 x 16B chunks, 256 thr x 4)
__device__ __forceinline__ void load_tile(uint32_t sbase, const char* g, int tid) {
#pragma unroll
    for (int j = 0; j < 4; j++) {
        int idx = tid + j * 256;          // 0..1023
        int r = idx >> 3, c = idx & 7;
        cp16(sbase + r * ROWB + c * 16, g + r * D_FIX + c * 16);
    }
}

// ---------------------------------------------------------------------------
// Persistent int8 IMMA kernel: 128x128x128 tiles, A resident, B double-buffered
// 8 warps, warp tile 64x32
// ---------------------------------------------------------------------------
__global__ __launch_bounds__(256, 2)
void xbm_i8_kernel(float* __restrict__ out) {
    extern __shared__ char smem[];
    const int tid = threadIdx.x, warp = tid >> 5, lane = tid & 31;
    const uint32_t sbase = smem_u32(smem);
    int*   labA_s = (int*)(smem + SM_LABA);
    float* wsum   = (float*)(smem + SM_WSUM);

    int t0 = blockIdx.x * TPC;
    int t1 = t0 + TPC;
    if (t1 > TOT_TILES) t1 = TOT_TILES;
    if (t0 >= t1) { return; }

    const int wm = (warp & 1) * 64;       // row offset of warp tile
    const int wn = (warp >> 1) * 32;      // col offset of warp tile

    // ldmatrix lane-invariant base addresses
    // A: x4 over 16 rows x 32B: lanes 0-15 rows, byte k0; lanes 16-31 rows, byte k0+16
    const uint32_t aBase = sbase + SM_A + (uint32_t)(wm + (lane & 15)) * ROWB
                         + ((lane >> 4) << 4);
    // B: x4 = two n8 groups: row = wn + (lane&7) + 8*(lane>>4), byte = 16*((lane>>3)&1) + k0
    const uint32_t bLane = (uint32_t)(wn + (lane & 7) + ((lane >> 4) << 3)) * ROWB
                         + (((lane >> 3) & 1) << 4);

    // prologue: A(nb0) + labA + B(t0) + labB(t0)
    int cur_nb = t0 >> 8;
    {
        int mb = t0 & 255, buf = t0 & 1;
        load_tile(sbase + SM_A, g_A8 + (size_t)cur_nb * 128 * D_FIX, tid);
        load_tile(sbase + SM_B0 + buf * TILE_SM, g_B8 + (size_t)mb * 128 * D_FIX, tid);
        if (tid < 32) {
            cp16(sbase + SM_LABA + tid * 16, g_labA + cur_nb * 128 + tid * 4);
            cp16(sbase + SM_LABB0 + buf * 512 + tid * 16, g_labB + mb * 128 + tid * 4);
        }
        cp_commit();
    }

    int la[8];                 // labels for this thread's 8 C-rows
    bool need_la = true;
    int accn = 0, accp = 0;    // integer loss accumulators

    for (int t = t0; t < t1; ++t) {
        cp_wait0();
        __syncthreads();                      // B(t) (+A) visible to all

        if ((t >> 8) != cur_nb) {             // A is stale for this tile: reload now
            cur_nb = t >> 8;
            load_tile(sbase + SM_A, g_A8 + (size_t)cur_nb * 128 * D_FIX, tid);
            if (tid < 32) cp16(sbase + SM_LABA + tid * 16, g_labA + cur_nb * 128 + tid * 4);
            cp_commit();
            cp_wait0();
            __syncthreads();
            need_la = true;
        }
        if (need_la) {
#pragma unroll
            for (int mi = 0; mi < 4; mi++) {
                la[mi * 2]     = labA_s[wm + mi * 16 + (lane >> 2)];
                la[mi * 2 + 1] = labA_s[wm + mi * 16 + (lane >> 2) + 8];
            }
            need_la = false;
        }

        const int buf = t & 1;
        const uint32_t bBase = sbase + (buf ? SM_B1 : SM_B0) + bLane;
        const int* labB_s = (const int*)(smem + (buf ? SM_LABB1 : SM_LABB0));

        // prefetch next B while computing (overwrites buf^1 = tile t-1's buffer)
        if (t + 1 < t1) {
            int nmb = (t + 1) & 255, nbuf = (t + 1) & 1;
            load_tile(sbase + SM_B0 + nbuf * TILE_SM, g_B8 + (size_t)nmb * 128 * D_FIX, tid);
            if (tid < 32) cp16(sbase + SM_LABB0 + nbuf * 512 + tid * 16,
                               g_labB + nmb * 128 + tid * 4);
            cp_commit();
        }

        // ---- compute 64x32 warp tile, K=128 ----
        int acc[4][4][4];
#pragma unroll
        for (int mi = 0; mi < 4; mi++)
#pragma unroll
            for (int ni = 0; ni < 4; ni++)
#pragma unroll
                for (int k = 0; k < 4; k++) acc[mi][ni][k] = 0;

#pragma unroll
        for (int k0 = 0; k0 < 128; k0 += 32) {
            uint32_t a[4][4], b[2][4];
#pragma unroll
            for (int mi = 0; mi < 4; mi++)
                ldsm_x4(a[mi], aBase + mi * (16 * ROWB) + k0);
#pragma unroll
            for (int p = 0; p < 2; p++)
                ldsm_x4(b[p], bBase + p * (16 * ROWB) + k0);
#pragma unroll
            for (int mi = 0; mi < 4; mi++)
#pragma unroll
                for (int ni = 0; ni < 4; ni++)
                    mma_s8(acc[mi][ni], a[mi],
                           b[ni >> 1][(ni & 1) * 2], b[ni >> 1][(ni & 1) * 2 + 1]);
        }

        // ---- integer epilogue from registers ----
        int lb[8];
#pragma unroll
        for (int ni = 0; ni < 4; ni++) {
            int col = wn + ni * 8 + ((lane & 3) << 1);
            lb[ni * 2]     = labB_s[col];
            lb[ni * 2 + 1] = labB_s[col + 1];
        }
#pragma unroll
        for (int mi = 0; mi < 4; mi++) {
#pragma unroll
            for (int ni = 0; ni < 4; ni++) {
#pragma unroll
                for (int k = 0; k < 4; k++) {
                    int s  = acc[mi][ni][k];
                    int lA = la[mi * 2 + (k >> 1)];
                    int lB = lb[ni * 2 + (k & 1)];
                    if (lA == lB) {
                        if (s < POS_T) accp += (s - POS_T);   // -(784 - s)
                    } else {
                        if (s > NEG_T) accn += s;
                    }
                }
            }
        }
    }

    // block reduce + single atomic
    float tsum = (float)accn - (float)accp;
#pragma unroll
    for (int off = 16; off > 0; off >>= 1)
        tsum += __shfl_down_sync(0xFFFFFFFFu, tsum, off);
    if (lane == 0) wsum[warp] = tsum;
    __syncthreads();
    if (tid == 0) {
        float s = 0.0f;
#pragma unroll
        for (int i = 0; i < 8; i++) s += wsum[i];
        atomicAdd(out, s * FINAL_SCALE);
    }
}

// ---------------------------------------------------------------------------
extern "C" void kernel_launch(void* const* d_in, const int* in_sizes, int n_in,
                              void* d_out, int out_size) {
    const float*     emb        = (const float*)d_in[0];
    const long long* labels     = (const long long*)d_in[1];
    const float*     ref        = (const float*)d_in[2];
    const long long* ref_labels = (const long long*)d_in[3];
    float* out = (float*)d_out;

    cudaFuncSetAttribute(xbm_i8_kernel,
                         cudaFuncAttributeMaxDynamicSharedMemorySize, SM_TOTAL);

    prep_kernel<<<512, 256>>>((const float4*)emb, labels, (const float4*)ref,
                              ref_labels, out);
    xbm_i8_kernel<<<CTAS, 256, SM_TOTAL>>>(out);
}

// round 6
// speedup vs baseline: 2.0718x; 2.0718x over previous
#include <cuda_runtime.h>
#include <cuda_bf16.h>
#include <cstdint>

// Problem shape: n=4096, m=32768, d=128
#define N_FIX 4096
#define M_FIX 32768
#define D_FIX 128
#define TOT_TILES 8192          // (4096/128) * (32768/128)
#define CTAS 304
#define TPC 27                  // ceil(8192/304)
#define MARGIN 0.5f
#define POS_THRESH (1.0f - 1e-5f)
#define INV_N (1.0f / 4096.0f)

#define ROWB 272                // padded smem row stride (bytes): 256B data + 16B pad
#define TILE_SM (128 * ROWB)    // 34816 B

// smem layout (bytes)
#define SM_A     0
#define SM_B0    34816
#define SM_B1    69632
#define SM_LABA  104448
#define SM_LABB0 104960
#define SM_LABB1 105472
#define SM_WSUM  105984
#define SM_TOTAL 106016

// bf16 scratch (allocation-free rule: __device__ globals)
__device__ __nv_bfloat16 g_A[N_FIX * D_FIX];
__device__ __nv_bfloat16 g_B[M_FIX * D_FIX];
__device__ int g_labA[N_FIX];
__device__ int g_labB[M_FIX];

// ---------------------------------------------------------------------------
// Prep: fp32 -> bf16, label extraction (level 0), out zeroing
// ---------------------------------------------------------------------------
__global__ void prep_kernel(const float4* __restrict__ emb,
                            const long long* __restrict__ labels,
                            const float4* __restrict__ ref,
                            const long long* __restrict__ ref_labels,
                            float* __restrict__ out) {
    int tid = blockIdx.x * blockDim.x + threadIdx.x;
    int stride = gridDim.x * blockDim.x;
    if (tid == 0) out[0] = 0.0f;
    for (int i = tid; i < N_FIX * D_FIX / 4; i += stride) {
        float4 v = emb[i];
        __nv_bfloat162* dst = (__nv_bfloat162*)&g_A[i * 4];
        dst[0] = __floats2bfloat162_rn(v.x, v.y);
        dst[1] = __floats2bfloat162_rn(v.z, v.w);
    }
    for (int i = tid; i < M_FIX * D_FIX / 4; i += stride) {
        float4 v = ref[i];
        __nv_bfloat162* dst = (__nv_bfloat162*)&g_B[i * 4];
        dst[0] = __floats2bfloat162_rn(v.x, v.y);
        dst[1] = __floats2bfloat162_rn(v.z, v.w);
    }
    for (int i = tid; i < N_FIX; i += stride)
        g_labA[i] = (int)labels[(long long)i * 2];
    for (int i = tid; i < M_FIX; i += stride)
        g_labB[i] = (int)ref_labels[(long long)i * 2];
}

// ---------------------------------------------------------------------------
// PTX helpers
// ---------------------------------------------------------------------------
__device__ __forceinline__ uint32_t smem_u32(const void* p) {
    return (uint32_t)__cvta_generic_to_shared(p);
}
__device__ __forceinline__ void cp16(uint32_t saddr, const void* gaddr) {
    asm volatile("cp.async.cg.shared.global [%0], [%1], 16;" :: "r"(saddr), "l"(gaddr));
}
__device__ __forceinline__ void cp_commit() { asm volatile("cp.async.commit_group;"); }
__device__ __forceinline__ void cp_wait0()  { asm volatile("cp.async.wait_group 0;" ::: "memory"); }

__device__ __forceinline__ void ldsm_x4(uint32_t* r, uint32_t addr) {
    asm volatile("ldmatrix.sync.aligned.m8n8.x4.shared.b16 {%0,%1,%2,%3}, [%4];"
                 : "=r"(r[0]), "=r"(r[1]), "=r"(r[2]), "=r"(r[3]) : "r"(addr));
}

__device__ __forceinline__ void mma_bf16(float* c, const uint32_t* a, uint32_t b0, uint32_t b1) {
    asm volatile(
        "mma.sync.aligned.m16n8k16.row.col.f32.bf16.bf16.f32 "
        "{%0,%1,%2,%3}, {%4,%5,%6,%7}, {%8,%9}, {%0,%1,%2,%3};"
        : "+f"(c[0]), "+f"(c[1]), "+f"(c[2]), "+f"(c[3])
        : "r"(a[0]), "r"(a[1]), "r"(a[2]), "r"(a[3]), "r"(b0), "r"(b1));
}

// load a 128x128 bf16 tile (rows of 256B) into padded smem: 2048 x 16B chunks
__device__ __forceinline__ void load_tile(uint32_t sbase, const __nv_bfloat16* g, int tid) {
#pragma unroll
    for (int j = 0; j < 8; j++) {
        int idx = tid + j * 256;          // 0..2047
        int r = idx >> 4, c = idx & 15;
        cp16(sbase + r * ROWB + c * 16, g + r * D_FIX + c * 8);
    }
}

// ---------------------------------------------------------------------------
// Persistent bf16 HMMA kernel: 128x128x128 tiles, A resident, B double-buffered
// 8 warps, warp tile 64x32
// ---------------------------------------------------------------------------
__global__ __launch_bounds__(256, 2)
void xbm_bf_kernel(float* __restrict__ out) {
    extern __shared__ char smem[];
    const int tid = threadIdx.x, warp = tid >> 5, lane = tid & 31;
    const uint32_t sbase = smem_u32(smem);
    int*   labA_s = (int*)(smem + SM_LABA);
    float* wsum   = (float*)(smem + SM_WSUM);

    int t0 = blockIdx.x * TPC;
    int t1 = t0 + TPC;
    if (t1 > TOT_TILES) t1 = TOT_TILES;
    if (t0 >= t1) { return; }

    const int wm = (warp & 1) * 64;       // row offset of warp tile
    const int wn = (warp >> 1) * 32;      // col offset of warp tile

    // ldmatrix lane-invariant base addresses (k-step advances +32 bytes)
    // A x4: lanes 0-15 rows wm+..+15 at byte 0, lanes 16-31 same rows at byte 16
    const uint32_t aBase = sbase + SM_A + (uint32_t)(wm + (lane & 15)) * ROWB
                         + ((lane >> 4) << 4);
    // B x4: m0 rows wn..+7 @0, m1 same @16, m2 rows wn+8..15 @0, m3 @16
    const uint32_t bLane = (uint32_t)(wn + (lane & 7) + ((lane >> 4) << 3)) * ROWB
                         + (((lane >> 3) & 1) << 4);

    // prologue: A(nb0) + labA + B(t0) + labB(t0)
    int cur_nb = t0 >> 8;
    {
        int mb = t0 & 255, buf = t0 & 1;
        load_tile(sbase + SM_A, g_A + (size_t)cur_nb * 128 * D_FIX, tid);
        load_tile(sbase + SM_B0 + buf * TILE_SM, g_B + (size_t)mb * 128 * D_FIX, tid);
        if (tid < 32) {
            cp16(sbase + SM_LABA + tid * 16, g_labA + cur_nb * 128 + tid * 4);
            cp16(sbase + SM_LABB0 + buf * 512 + tid * 16, g_labB + mb * 128 + tid * 4);
        }
        cp_commit();
    }

    int la[8];                 // labels for this thread's 8 C-rows
    bool need_la = true;
    float tsum = 0.0f;

    for (int t = t0; t < t1; ++t) {
        cp_wait0();
        __syncthreads();                      // B(t) (+A) visible to all

        if ((t >> 8) != cur_nb) {             // A is stale for this tile: reload now
            cur_nb = t >> 8;
            load_tile(sbase + SM_A, g_A + (size_t)cur_nb * 128 * D_FIX, tid);
            if (tid < 32) cp16(sbase + SM_LABA + tid * 16, g_labA + cur_nb * 128 + tid * 4);
            cp_commit();
            cp_wait0();
            __syncthreads();
            need_la = true;
        }
        if (need_la) {
#pragma unroll
            for (int mi = 0; mi < 4; mi++) {
                la[mi * 2]     = labA_s[wm + mi * 16 + (lane >> 2)];
                la[mi * 2 + 1] = labA_s[wm + mi * 16 + (lane >> 2) + 8];
            }
            need_la = false;
        }

        const int buf = t & 1;
        const uint32_t bBase = sbase + (buf ? SM_B1 : SM_B0) + bLane;
        const int* labB_s = (const int*)(smem + (buf ? SM_LABB1 : SM_LABB0));

        // prefetch next B while computing (overwrites buf^1 = tile t-1's buffer)
        if (t + 1 < t1) {
            int nmb = (t + 1) & 255, nbuf = (t + 1) & 1;
            load_tile(sbase + SM_B0 + nbuf * TILE_SM, g_B + (size_t)nmb * 128 * D_FIX, tid);
            if (tid < 32) cp16(sbase + SM_LABB0 + nbuf * 512 + tid * 16,
                               g_labB + nmb * 128 + tid * 4);
            cp_commit();
        }

        // ---- compute 64x32 warp tile, K=128 (8 k-steps of 16) ----
        float acc[4][4][4];
#pragma unroll
        for (int mi = 0; mi < 4; mi++)
#pragma unroll
            for (int ni = 0; ni < 4; ni++)
#pragma unroll
                for (int k = 0; k < 4; k++) acc[mi][ni][k] = 0.0f;

#pragma unroll
        for (int ks = 0; ks < 8; ks++) {
            const int k0 = ks * 32;            // byte offset
            uint32_t a[4][4], b[2][4];
#pragma unroll
            for (int mi = 0; mi < 4; mi++)
                ldsm_x4(a[mi], aBase + mi * (16 * ROWB) + k0);
#pragma unroll
            for (int p = 0; p < 2; p++)
                ldsm_x4(b[p], bBase + p * (16 * ROWB) + k0);
#pragma unroll
            for (int mi = 0; mi < 4; mi++)
#pragma unroll
                for (int ni = 0; ni < 4; ni++)
                    mma_bf16(acc[mi][ni], a[mi],
                             b[ni >> 1][(ni & 1) * 2], b[ni >> 1][(ni & 1) * 2 + 1]);
        }

        // ---- epilogue from registers ----
        int lb[8];
#pragma unroll
        for (int ni = 0; ni < 4; ni++) {
            int col = wn + ni * 8 + ((lane & 3) << 1);
            lb[ni * 2]     = labB_s[col];
            lb[ni * 2 + 1] = labB_s[col + 1];
        }
#pragma unroll
        for (int mi = 0; mi < 4; mi++) {
#pragma unroll
            for (int ni = 0; ni < 4; ni++) {
#pragma unroll
                for (int k = 0; k < 4; k++) {
                    float s = acc[mi][ni][k];
                    int lA = la[mi * 2 + (k >> 1)];
                    int lB = lb[ni * 2 + (k & 1)];
                    if (lA == lB) {
                        if (s < POS_THRESH) tsum += 1.0f - s;
                    } else {
                        if (s > MARGIN) tsum += s;
                    }
                }
            }
        }
    }

    // block reduce + single atomic
#pragma unroll
    for (int off = 16; off > 0; off >>= 1)
        tsum += __shfl_down_sync(0xFFFFFFFFu, tsum, off);
    if (lane == 0) wsum[warp] = tsum;
    __syncthreads();
    if (tid == 0) {
        float s = 0.0f;
#pragma unroll
        for (int i = 0; i < 8; i++) s += wsum[i];
        atomicAdd(out, s * INV_N);
    }
}

// ---------------------------------------------------------------------------
extern "C" void kernel_launch(void* const* d_in, const int* in_sizes, int n_in,
                              void* d_out, int out_size) {
    const float*     emb        = (const float*)d_in[0];
    const long long* labels     = (const long long*)d_in[1];
    const float*     ref        = (const float*)d_in[2];
    const long long* ref_labels = (const long long*)d_in[3];
    float* out = (float*)d_out;

    cudaFuncSetAttribute(xbm_bf_kernel,
                         cudaFuncAttributeMaxDynamicSharedMemorySize, SM_TOTAL);

    prep_kernel<<<512, 256>>>((const float4*)emb, labels, (const float4*)ref,
                              ref_labels, out);
    xbm_bf_kernel<<<CTAS, 256, SM_TOTAL>>>(out);
}

// round 7
// speedup vs baseline: 2.1679x; 1.0464x over previous
#include <cuda_runtime.h>
#include <cuda_bf16.h>
#include <cstdint>

// Problem shape: n=4096, m=32768, d=128
#define N_FIX 4096
#define M_FIX 32768
#define D_FIX 128
#define TOT_TILES 8192          // (4096/128) * (32768/128)
#define CTAS 304
#define TPC 27                  // ceil(8192/304)
#define MARGIN 0.5f
#define INV_N (1.0f / 4096.0f)

#define ROWB 272                // padded smem row stride (bytes): 256B data + 16B pad
#define TILE_SM (128 * ROWB)    // 34816 B

// smem layout (bytes)
#define SM_A     0
#define SM_B0    34816
#define SM_B1    69632
#define SM_LABA  104448
#define SM_LABB0 104960
#define SM_LABB1 105472
#define SM_WSUM  105984         // 16 floats
#define SM_TOTAL 106048

// bf16 scratch (allocation-free rule: __device__ globals)
__device__ __nv_bfloat16 g_A[N_FIX * D_FIX];
__device__ __nv_bfloat16 g_B[M_FIX * D_FIX];
__device__ int g_labA[N_FIX];
__device__ int g_labB[M_FIX];

// ---------------------------------------------------------------------------
// Prep: fp32 -> bf16, label extraction (level 0), out zeroing
// ---------------------------------------------------------------------------
__global__ void prep_kernel(const float4* __restrict__ emb,
                            const long long* __restrict__ labels,
                            const float4* __restrict__ ref,
                            const long long* __restrict__ ref_labels,
                            float* __restrict__ out) {
    int tid = blockIdx.x * blockDim.x + threadIdx.x;
    int stride = gridDim.x * blockDim.x;
    if (tid == 0) out[0] = 0.0f;
    for (int i = tid; i < N_FIX * D_FIX / 4; i += stride) {
        float4 v = emb[i];
        __nv_bfloat162* dst = (__nv_bfloat162*)&g_A[i * 4];
        dst[0] = __floats2bfloat162_rn(v.x, v.y);
        dst[1] = __floats2bfloat162_rn(v.z, v.w);
    }
    for (int i = tid; i < M_FIX * D_FIX / 4; i += stride) {
        float4 v = ref[i];
        __nv_bfloat162* dst = (__nv_bfloat162*)&g_B[i * 4];
        dst[0] = __floats2bfloat162_rn(v.x, v.y);
        dst[1] = __floats2bfloat162_rn(v.z, v.w);
    }
    for (int i = tid; i < N_FIX; i += stride)
        g_labA[i] = (int)labels[(long long)i * 2];
    for (int i = tid; i < M_FIX; i += stride)
        g_labB[i] = (int)ref_labels[(long long)i * 2];
}

// ---------------------------------------------------------------------------
// PTX helpers
// ---------------------------------------------------------------------------
__device__ __forceinline__ uint32_t smem_u32(const void* p) {
    return (uint32_t)__cvta_generic_to_shared(p);
}
__device__ __forceinline__ void cp16(uint32_t saddr, const void* gaddr) {
    asm volatile("cp.async.cg.shared.global [%0], [%1], 16;" :: "r"(saddr), "l"(gaddr));
}
__device__ __forceinline__ void cp_commit() { asm volatile("cp.async.commit_group;"); }
__device__ __forceinline__ void cp_wait0()  { asm volatile("cp.async.wait_group 0;" ::: "memory"); }

__device__ __forceinline__ void ldsm_x4(uint32_t* r, uint32_t addr) {
    asm volatile("ldmatrix.sync.aligned.m8n8.x4.shared.b16 {%0,%1,%2,%3}, [%4];"
                 : "=r"(r[0]), "=r"(r[1]), "=r"(r[2]), "=r"(r[3]) : "r"(addr));
}

__device__ __forceinline__ void mma_bf16(float* c, const uint32_t* a, uint32_t b0, uint32_t b1) {
    asm volatile(
        "mma.sync.aligned.m16n8k16.row.col.f32.bf16.bf16.f32 "
        "{%0,%1,%2,%3}, {%4,%5,%6,%7}, {%8,%9}, {%0,%1,%2,%3};"
        : "+f"(c[0]), "+f"(c[1]), "+f"(c[2]), "+f"(c[3])
        : "r"(a[0]), "r"(a[1]), "r"(a[2]), "r"(a[3]), "r"(b0), "r"(b1));
}

// load a 128x128 bf16 tile (rows of 256B) into padded smem: 2048 x 16B chunks
__device__ __forceinline__ void load_tile(uint32_t sbase, const __nv_bfloat16* g, int tid) {
#pragma unroll
    for (int j = 0; j < 4; j++) {
        int idx = tid + j * 512;          // 0..2047
        int r = idx >> 4, c = idx & 15;
        cp16(sbase + r * ROWB + c * 16, g + r * D_FIX + c * 8);
    }
}

// ---------------------------------------------------------------------------
// Persistent bf16 HMMA kernel: 128x128x128 tiles, A resident, B double-buffered
// 512 threads = 16 warps, warp tile 32x32 (4x4 warp grid)
// ---------------------------------------------------------------------------
__global__ __launch_bounds__(512, 2)
void xbm_bf_kernel(float* __restrict__ out) {
    extern __shared__ char smem[];
    const int tid = threadIdx.x, warp = tid >> 5, lane = tid & 31;
    const uint32_t sbase = smem_u32(smem);
    const int* labA_s = (const int*)(smem + SM_LABA);
    float* wsum = (float*)(smem + SM_WSUM);

    int t0 = blockIdx.x * TPC;
    int t1 = t0 + TPC;
    if (t1 > TOT_TILES) t1 = TOT_TILES;
    if (t0 >= t1) { return; }

    const int wm = (warp & 3) * 32;       // row offset of warp tile
    const int wn = (warp >> 2) * 32;      // col offset of warp tile

    // ldmatrix lane-invariant base addresses (k-step advances +32 bytes)
    const uint32_t aBase = sbase + SM_A + (uint32_t)(wm + (lane & 15)) * ROWB
                         + ((lane >> 4) << 4);
    const uint32_t bLane = (uint32_t)(wn + (lane & 7) + ((lane >> 4) << 3)) * ROWB
                         + (((lane >> 3) & 1) << 4);

    // epilogue label indices for this thread
    const int rowA0 = wm + (lane >> 2);           // +8, +16, +24 for others
    const int colB0 = wn + ((lane & 3) << 1);     // pairs, +8 per ni

    // prologue: A(nb0) + labA + B(t0) + labB(t0)
    int cur_nb = t0 >> 8;
    {
        int mb = t0 & 255, buf = t0 & 1;
        load_tile(sbase + SM_A, g_A + (size_t)cur_nb * 128 * D_FIX, tid);
        load_tile(sbase + SM_B0 + buf * TILE_SM, g_B + (size_t)mb * 128 * D_FIX, tid);
        if (tid < 32) {
            cp16(sbase + SM_LABA + tid * 16, g_labA + cur_nb * 128 + tid * 4);
            cp16(sbase + SM_LABB0 + buf * 512 + tid * 16, g_labB + mb * 128 + tid * 4);
        }
        cp_commit();
    }

    float ts[4] = {0.0f, 0.0f, 0.0f, 0.0f};   // 4 independent chains, reduced at end

    for (int t = t0; t < t1; ++t) {
        cp_wait0();
        __syncthreads();                      // B(t) (+A) visible to all

        if ((t >> 8) != cur_nb) {             // A is stale for this tile: reload now
            cur_nb = t >> 8;
            load_tile(sbase + SM_A, g_A + (size_t)cur_nb * 128 * D_FIX, tid);
            if (tid < 32) cp16(sbase + SM_LABA + tid * 16, g_labA + cur_nb * 128 + tid * 4);
            cp_commit();
            cp_wait0();
            __syncthreads();
        }

        const int buf = t & 1;
        const uint32_t bBase = sbase + (buf ? SM_B1 : SM_B0) + bLane;
        const int* labB_s = (const int*)(smem + (buf ? SM_LABB1 : SM_LABB0));

        // prefetch next B while computing (overwrites buf^1 = tile t-1's buffer)
        if (t + 1 < t1) {
            int nmb = (t + 1) & 255, nbuf = (t + 1) & 1;
            load_tile(sbase + SM_B0 + nbuf * TILE_SM, g_B + (size_t)nmb * 128 * D_FIX, tid);
            if (tid < 32) cp16(sbase + SM_LABB0 + nbuf * 512 + tid * 16,
                               g_labB + nmb * 128 + tid * 4);
            cp_commit();
        }

        // ---- compute 32x32 warp tile, K=128 (8 k-steps of 16) ----
        float acc[2][4][4];
#pragma unroll
        for (int mi = 0; mi < 2; mi++)
#pragma unroll
            for (int ni = 0; ni < 4; ni++)
#pragma unroll
                for (int k = 0; k < 4; k++) acc[mi][ni][k] = 0.0f;

#pragma unroll
        for (int ks = 0; ks < 8; ks++) {
            const int k0 = ks * 32;            // byte offset
            uint32_t a[2][4], b[2][4];
#pragma unroll
            for (int mi = 0; mi < 2; mi++)
                ldsm_x4(a[mi], aBase + mi * (16 * ROWB) + k0);
#pragma unroll
            for (int p = 0; p < 2; p++)
                ldsm_x4(b[p], bBase + p * (16 * ROWB) + k0);
#pragma unroll
            for (int mi = 0; mi < 2; mi++)
#pragma unroll
                for (int ni = 0; ni < 4; ni++)
                    mma_bf16(acc[mi][ni], a[mi],
                             b[ni >> 1][(ni & 1) * 2], b[ni >> 1][(ni & 1) * 2 + 1]);
        }

        // ---- epilogue: branchless, 4 independent accumulator chains ----
#pragma unroll
        for (int mi = 0; mi < 2; mi++) {
            const int la0 = labA_s[rowA0 + mi * 16];
            const int la1 = labA_s[rowA0 + mi * 16 + 8];
#pragma unroll
            for (int ni = 0; ni < 4; ni++) {
                const int lb0 = labB_s[colB0 + ni * 8];
                const int lb1 = labB_s[colB0 + ni * 8 + 1];
#pragma unroll
                for (int k = 0; k < 4; k++) {
                    const float s = acc[mi][ni][k];
                    const int lA = (k >> 1) ? la1 : la0;
                    const int lB = (k & 1) ? lb1 : lb0;
                    float v;
                    if (lA == lB) v = fmaxf(1.0f - s, 0.0f);
                    else          v = (s > MARGIN) ? s : 0.0f;
                    ts[k] += v;
                }
            }
        }
    }

    // block reduce + single atomic
    float tsum = (ts[0] + ts[1]) + (ts[2] + ts[3]);
#pragma unroll
    for (int off = 16; off > 0; off >>= 1)
        tsum += __shfl_down_sync(0xFFFFFFFFu, tsum, off);
    if (lane == 0) wsum[warp] = tsum;
    __syncthreads();
    if (tid == 0) {
        float s = 0.0f;
#pragma unroll
        for (int i = 0; i < 16; i++) s += wsum[i];
        atomicAdd(out, s * INV_N);
    }
}

// ---------------------------------------------------------------------------
extern "C" void kernel_launch(void* const* d_in, const int* in_sizes, int n_in,
                              void* d_out, int out_size) {
    const float*     emb        = (const float*)d_in[0];
    const long long* labels     = (const long long*)d_in[1];
    const float*     ref        = (const float*)d_in[2];
    const long long* ref_labels = (const long long*)d_in[3];
    float* out = (float*)d_out;

    cudaFuncSetAttribute(xbm_bf_kernel,
                         cudaFuncAttributeMaxDynamicSharedMemorySize, SM_TOTAL);

    prep_kernel<<<512, 256>>>((const float4*)emb, labels, (const float4*)ref,
                              ref_labels, out);
    xbm_bf_kernel<<<CTAS, 512, SM_TOTAL>>>(out);
}